// round 4
// baseline (speedup 1.0000x reference)
#include <cuda_runtime.h>
#include <math.h>
#include <float.h>

#define BB 64
#define NN 32768
#define CC 2
#define KK 10
#define QT 8                 // chunks per batch row (one block each)
#define CHUNK (NN / QT)      // 4096 columns per block
#define SEG 2048             // columns per smem tile
#define NTILE (CHUNK / SEG)  // 2
#define NWARP 10
#define NTHR (NWARP * 32)    // 320
#define FULLM 0xffffffffu
#define MAXC 0x7fffffff

static __device__ __forceinline__ float sigmoidf_(float x) {
    return 1.0f / (1.0f + expf(-x));
}
static __device__ __forceinline__ float softplusf_(float x) {
    return fmaxf(x, 0.0f) + log1pf(expf(-fabsf(x)));
}

// partial top-10 per (batch, row, chunk)
__device__ float g_part_val[BB * KK * QT * KK];
__device__ int   g_part_col[BB * KK * QT * KK];
// per-batch loss partials + completion counter
__device__ float g_bpart[BB];
__device__ float g_bm[BB];
__device__ int   g_done;

// ---------------------------------------------------------------------------
// Warp-collective: merge smem candidate buffer (cnt <= 64) + current
// distributed top-10 (lane j < 10 holds j-th best) -> new top-10 + tau.
// Lexicographic (val, col) ascending, matching jnp.argmin flat-index ties.
// ---------------------------------------------------------------------------
static __device__ __forceinline__ void merge10(float& lv, int& lc, float& tau,
                                               int cnt, const float* bv,
                                               const int* bc, int lane) {
    __syncwarp();
    float v0 = (lane < cnt) ? bv[lane] : FLT_MAX;
    int   c0 = (lane < cnt) ? bc[lane] : MAXC;
    float v1 = (lane + 32 < cnt) ? bv[lane + 32] : FLT_MAX;
    int   c1 = (lane + 32 < cnt) ? bc[lane + 32] : MAXC;
    float v2 = lv;  // lanes >= 10 already FLT_MAX
    int   c2 = lc;
    float nv = FLT_MAX; int nc = MAXC;
#pragma unroll
    for (int r = 0; r < KK; r++) {
        float mv = v0; int mc = c0; int sl = 0;
        if (v1 < mv || (v1 == mv && c1 < mc)) { mv = v1; mc = c1; sl = 1; }
        if (v2 < mv || (v2 == mv && c2 < mc)) { mv = v2; mc = c2; sl = 2; }
        int src = lane;
#pragma unroll
        for (int o = 16; o; o >>= 1) {
            float ov = __shfl_xor_sync(FULLM, mv, o);
            int   oc = __shfl_xor_sync(FULLM, mc, o);
            int   os = __shfl_xor_sync(FULLM, src, o);
            if (ov < mv || (ov == mv && oc < mc)) { mv = ov; mc = oc; src = os; }
        }
        if (lane == src) {  // kill the consumed slot on the winning lane
            if (sl == 0)      { v0 = FLT_MAX; c0 = MAXC; }
            else if (sl == 1) { v1 = FLT_MAX; c1 = MAXC; }
            else              { v2 = FLT_MAX; c2 = MAXC; }
        }
        if (lane == r) { nv = mv; nc = mc; }
    }
    lv = nv; lc = nc;
    tau = __shfl_sync(FULLM, lv, KK - 1);
}

// ---------------------------------------------------------------------------
// Kernel A: fused features + buffered top-10. Block = (batch, chunk).
// 10 warps: all fill the feature tile, then warp w scans GT row w.
// ---------------------------------------------------------------------------
__global__ __launch_bounds__(NTHR) void fused_topk_kernel(
        const float* __restrict__ ps,
        const float* __restrict__ pe,
        const float* __restrict__ pcl,
        const float* __restrict__ gt) {
    __shared__ float4 feat[SEG];          // 32KB: (s, e, h0, h1)
    __shared__ float  bufv[NWARP][64];    // per-warp candidate buffer
    __shared__ int    bufc[NWARP][64];

    int b = blockIdx.x >> 3;
    int chunk = blockIdx.x & (QT - 1);
    int cbase = chunk * CHUNK;
    int w = threadIdx.x >> 5;
    int lane = threadIdx.x & 31;

    const float* g = gt + (size_t)(b * KK + w) * 3;
    float fs = g[0], fe = g[1], cl = g[2];
    bool present = !((fs != fs) || (fe != fe) || (cl != cl));
    int cli = 0;
    float ms = 0.0f, me = 0.0f;
    if (present) {
        int ci = (int)cl;
        cli = ci < 0 ? 0 : (ci > CC - 1 ? CC - 1 : ci);
        ms = -2.0f * fs;
        me = -2.0f * fe;
    }

    float lv = FLT_MAX; int lc = MAXC;   // lane j<10: j-th best (shifted val)
    float tau = FLT_MAX;
    int cnt = 0;

    const float2* pcl2 = reinterpret_cast<const float2*>(pcl);

    for (int t = 0; t < NTILE; t++) {
        int colbase = cbase + t * SEG;
        size_t gb = (size_t)b * NN + colbase;

        // ---- feature phase: all 320 threads ----
        for (int i = threadIdx.x; i < SEG; i += NTHR) {
            float s = sigmoidf_(ps[gb + i]);
            float e = sigmoidf_(pe[gb + i]);
            float2 l = pcl2[gb + i];
            float c0 = sigmoidf_(l.x);
            float c1 = sigmoidf_(l.y);
            float base = fmaf(s, s, fmaf(e, e, fmaf(c0, c0, fmaf(c1, c1, 1.0f))));
            feat[i] = make_float4(s, e, base - 2.0f * c0, base - 2.0f * c1);
        }
        __syncthreads();

        // ---- scan phase: warp w scans row w ----
        if (present) {
#pragma unroll 4
            for (int r = 0; r < SEG / 32; r++) {
                int i = r * 32 + lane;
                float4 f = feat[i];
                float h = (cli == 0) ? f.z : f.w;
                float v = fmaf(f.x, ms, fmaf(f.y, me, h));
                unsigned bal = __ballot_sync(FULLM, v <= tau);
                if (bal) {
                    if (v <= tau) {
                        int pos = cnt + __popc(bal & ((1u << lane) - 1u));
                        bufv[w][pos] = v;
                        bufc[w][pos] = colbase + i;
                    }
                    cnt += __popc(bal);
                    if (cnt > 32) {
                        merge10(lv, lc, tau, cnt, bufv[w], bufc[w], lane);
                        cnt = 0;
                    }
                }
            }
        }
        __syncthreads();
    }

    if (present && cnt) merge10(lv, lc, tau, cnt, bufv[w], bufc[w], lane);

    if (lane < KK) {
        int ob = ((b * KK + w) * QT + chunk) * KK + lane;
        if (present) {
            g_part_val[ob] = lv + fmaf(fs, fs, fe * fe);  // restore row constant
            g_part_col[ob] = lc;
        } else {
            g_part_val[ob] = 1.0e6f;                      // sentinel (never valid)
            g_part_col[ob] = cbase + lane;
        }
    }
}

// ---------------------------------------------------------------------------
// Kernel B: per-batch merge (warp per row, 80 partials) + greedy match +
// losses + fused final reduction (last block).
// ---------------------------------------------------------------------------
__global__ __launch_bounds__(NTHR) void merge_match_kernel(
        const float* __restrict__ ps,
        const float* __restrict__ pe,
        const float* __restrict__ pcl,
        const float* __restrict__ pcf,
        const float* __restrict__ gt,
        float* __restrict__ out) {
    __shared__ float sval[KK * KK];
    __shared__ int   scol[KK * KK];
    __shared__ float s_fs[KK], s_fe[KK];
    __shared__ int   s_cli[KK];
    __shared__ int   s_mk[KK], s_mcol[KK];
    __shared__ int   s_nm;
    __shared__ float s_loss[KK];

    int b = blockIdx.x;
    int w = threadIdx.x >> 5;
    int lane = threadIdx.x & 31;

    // ---- merge 80 partials -> sorted top-10 per row (3 slots per lane) ----
    {
        int ib = (b * KK + w) * (QT * KK);  // 80 entries
        float v0 = g_part_val[ib + lane];
        int   c0 = g_part_col[ib + lane];
        float v1 = g_part_val[ib + 32 + lane];
        int   c1 = g_part_col[ib + 32 + lane];
        float v2 = (lane < QT * KK - 64) ? g_part_val[ib + 64 + lane] : FLT_MAX;
        int   c2 = (lane < QT * KK - 64) ? g_part_col[ib + 64 + lane] : MAXC;
#pragma unroll
        for (int r = 0; r < KK; r++) {
            float mv = v0; int mc = c0; int sl = 0;
            if (v1 < mv || (v1 == mv && c1 < mc)) { mv = v1; mc = c1; sl = 1; }
            if (v2 < mv || (v2 == mv && c2 < mc)) { mv = v2; mc = c2; sl = 2; }
            int src = lane;
#pragma unroll
            for (int o = 16; o; o >>= 1) {
                float ov = __shfl_xor_sync(FULLM, mv, o);
                int   oc = __shfl_xor_sync(FULLM, mc, o);
                int   os = __shfl_xor_sync(FULLM, src, o);
                if (ov < mv || (ov == mv && oc < mc)) { mv = ov; mc = oc; src = os; }
            }
            if (lane == src) {
                if (sl == 0)      { v0 = FLT_MAX; c0 = MAXC; }
                else if (sl == 1) { v1 = FLT_MAX; c1 = MAXC; }
                else              { v2 = FLT_MAX; c2 = MAXC; }
            }
            if (lane == 0) { sval[w * KK + r] = mv; scol[w * KK + r] = mc; }
        }
    }
    if (threadIdx.x < KK) {
        const float* g = gt + (size_t)(b * KK + threadIdx.x) * 3;
        float a = g[0], c = g[1], d = g[2];
        bool pres = !((a != a) || (c != c) || (d != d));
        s_fs[threadIdx.x] = (a != a) ? 0.0f : a;
        s_fe[threadIdx.x] = (c != c) ? 0.0f : c;
        d = (d != d) ? 0.0f : d;
        int ci = (int)d;
        ci = ci < 0 ? 0 : (ci > CC - 1 ? CC - 1 : ci);
        s_cli[threadIdx.x] = pres ? ci : -1;   // -1 = absent
    }
    __syncthreads();

    // ---- greedy match (thread 0, all in smem) ----
    if (threadIdx.x == 0) {
        bool rowdone[KK];
        int used[KK]; int nused = 0;
        int nm = 0;
#pragma unroll
        for (int k = 0; k < KK; k++) rowdone[k] = false;

        for (int it = 0; it < KK; it++) {
            float bvv = FLT_MAX; int bk = -1, bcol = -1;
            for (int k = 0; k < KK; k++) {              // ascending row = flat-idx ties
                if (s_cli[k] < 0 || rowdone[k]) continue;
                for (int j = 0; j < KK; j++) {          // sorted by (val, col)
                    int col = scol[k * KK + j];
                    bool isused = false;
                    for (int u = 0; u < nused; u++) isused |= (used[u] == col);
                    if (isused) continue;
                    float v = sval[k * KK + j];
                    if (v < bvv) { bvv = v; bk = k; bcol = col; }
                    break;                               // first unmasked = row min
                }
            }
            if (bk < 0) break;
            rowdone[bk] = true; used[nused++] = bcol;
            if (bvv < 0.5e6f) { s_mk[nm] = bk; s_mcol[nm] = bcol; nm++; }
        }
        s_nm = nm;
    }
    __syncthreads();

    // ---- exact loss terms in parallel ----
    int nm = s_nm;
    if (threadIdx.x < KK) {
        float part = 0.0f;
        if (threadIdx.x < nm) {
            int k = s_mk[threadIdx.x];
            int col = s_mcol[threadIdx.x];
            size_t idx = (size_t)b * NN + col;
            float ss = sigmoidf_(ps[idx]);
            float se = sigmoidf_(pe[idx]);
            float gs = s_fs[k], ge = s_fe[k];
            float dls = ss - gs, dle = se - ge;
            part = dls * dls + dle * dle;                           // loc
            float l0 = pcl[idx * 2], l1 = pcl[idx * 2 + 1];
            part += (s_cli[k] == 0) ? (softplusf_(-l0) + softplusf_(l1))
                                    : (softplusf_(l0) + softplusf_(-l1));  // class
            float a1 = fminf(ss, se), b1 = fmaxf(ss, se);
            float a2 = fminf(gs, ge), b2 = fmaxf(gs, ge);
            float inter = fmaxf(0.0f, fminf(b1, b2) - fmaxf(a1, a2));
            float uni = fmaxf(1e-8f, fmaxf(b1, b2) - fminf(a1, a2));
            float iou = inter / uni;
            float dcf = sigmoidf_(pcf[idx]) - iou;
            part += dcf * dcf;                                      // conf
        }
        s_loss[threadIdx.x] = part;
    }
    __syncthreads();

    if (threadIdx.x == 0) {
        float tot = 0.0f;
#pragma unroll
        for (int j = 0; j < KK; j++) tot += s_loss[j];
        g_bpart[b] = tot;
        g_bm[b] = (float)nm;
        __threadfence();
        int t = atomicAdd(&g_done, 1);
        if (t == BB - 1) {                 // last block: fused finalize
            g_done = 0;                    // reset for next graph replay
            float P = 0.0f, M = 0.0f;
            for (int i = 0; i < BB; i++) { P += g_bpart[i]; M += g_bm[i]; }
            out[0] = (M > 0.0f) ? (P / (M + 1e-8f)) : 0.0f;
        }
    }
}

// ---------------------------------------------------------------------------
extern "C" void kernel_launch(void* const* d_in, const int* in_sizes, int n_in,
                              void* d_out, int out_size) {
    const float* ps  = (const float*)d_in[0];   // (B, N)
    const float* pe  = (const float*)d_in[1];   // (B, N)
    const float* pcl = (const float*)d_in[2];   // (B, N, 2)
    const float* pcf = (const float*)d_in[3];   // (B, N)
    const float* gt  = (const float*)d_in[4];   // (B, K, 3)
    float* out = (float*)d_out;

    fused_topk_kernel<<<BB * QT, NTHR>>>(ps, pe, pcl, gt);
    merge_match_kernel<<<BB, NTHR>>>(ps, pe, pcl, pcf, gt, out);
}